// round 16
// baseline (speedup 1.0000x reference)
#include <cuda_runtime.h>
#include <cstdint>

#define BB 8
#define HH 64
#define WW 64

// Scratch: qkv [32768 x 768] (tf32 bits, q pre-scaled), y [32768 x 256],
// tf32-rounded copies of x and weights, bias tables in mma-frag order.
__device__ float g_qkv[25165824];
__device__ float g_y[8388608];
__device__ float g_xt[8388608];
__device__ float g_wt[262144];       // w_qkv_t [768x256] + w_proj_t [256x256]
__device__ float g_bias7[3670016];   // 4h*64t*4w*32l*28nt*4
__device__ float g_bias13[7864320];  // 4h*64t*4w*32l*50nt*4 (6553600 used)

__device__ __forceinline__ uint32_t f2tf32(float x) {
    uint32_t u;
    asm("cvt.rna.tf32.f32 %0, %1;" : "=r"(u) : "f"(x));
    return u;
}
__device__ __forceinline__ int iclamp(int v, int lo, int hi) {
    return min(max(v, lo), hi);
}
__device__ __forceinline__ uint32_t smem_u32(const void* p) {
    uint32_t a;
    asm("{ .reg .u64 t; cvta.to.shared.u64 t, %1; cvt.u32.u64 %0, t; }"
        : "=r"(a) : "l"(p));
    return a;
}

// ---------------------------------------------------------------------------
// Prep: rounding (QKV dependency) and bias tables (natten dependency) are
// SEPARATE kernels so the bias work can overlap the QKV GEMM on stream 2.
// ---------------------------------------------------------------------------
__device__ __forceinline__ void round_body(const float4* __restrict__ src,
                                           float4* __restrict__ dst,
                                           int i, int n4)
{
    if (i >= n4) return;
    float4 v = __ldg(&src[i]);
    v.x = __uint_as_float(f2tf32(v.x));
    v.y = __uint_as_float(f2tf32(v.y));
    v.z = __uint_as_float(f2tf32(v.z));
    v.w = __uint_as_float(f2tf32(v.w));
    dst[i] = v;
}

// ranges: [0,8192) round x | [8192,8384) round wq | [8384,8448) round wp
__global__ __launch_bounds__(256)
void prep_round(const float* __restrict__ x,
                const float* __restrict__ w_qkv,
                const float* __restrict__ w_proj,
                float* __restrict__ xt, float* __restrict__ wqt,
                float* __restrict__ wpt)
{
    const int bx = blockIdx.x;
    const int tid = threadIdx.x;
    if (bx < 8192) {
        round_body((const float4*)x, (float4*)xt, bx * 256 + tid, 2097152);
    } else if (bx < 8384) {
        round_body((const float4*)w_qkv, (float4*)wqt, (bx - 8192) * 256 + tid, 49152);
    } else {
        round_body((const float4*)w_proj, (float4*)wpt, (bx - 8384) * 256 + tid, 16384);
    }
}

template<int K, int UXP, int UXR, int NTILES>
__device__ __forceinline__ void bias_body(const float* __restrict__ rpb,
                                          float* __restrict__ table, int gid)
{
    constexpr int NH = K / 2;
    constexpr int RP = 2 * K - 1;
    constexpr int UY = K + 7;
    const int t    = gid % NTILES;
    int r1 = gid / NTILES;
    const int lane = r1 & 31; r1 >>= 5;
    const int w    = r1 & 3;  r1 >>= 2;
    const int tile = r1 & 63; r1 >>= 6;
    const int h    = r1;
    const int ty = tile >> 3, tx = tile & 7;
    const int lr = lane >> 2, lc = lane & 3;
    const int uy0 = iclamp(ty * 8 - NH, 0, HH - UY);
    const int ux0 = iclamp(tx * 8 - NH, 0, WW - UY);

    float v[4];
#pragma unroll
    for (int r = 0; r < 4; r++) {
        const int m = w * 16 + lr + ((r >> 1) << 3);
        const int n = t * 8 + (lc << 1) + (r & 1);
        const int i = ty * 8 + (m >> 3);
        const int j = tx * 8 + (m & 7);
        const int si = iclamp(i - NH, 0, HH - K);
        const int sj = iclamp(j - NH, 0, WW - K);
        const int uy = n / UXP, ux = n % UXP;
        const int y = uy0 + uy, x = ux0 + ux;
        bool ok = (ux < UXR) && (y >= si) && (y < si + K) && (x >= sj) && (x < sj + K);
        v[r] = ok ? rpb[((size_t)h * RP + (y - i + K - 1)) * RP + (x - j + K - 1)]
                  : -1e30f;
    }
    *(float4*)&table[(size_t)gid * 4] = make_float4(v[0], v[1], v[2], v[3]);
}

// ranges: [0,3584) bias7 | [3584,9984) bias13
__global__ __launch_bounds__(256)
void prep_bias(const float* __restrict__ rpb0,
               const float* __restrict__ rpb1,
               float* __restrict__ bt7, float* __restrict__ bt13)
{
    const int bx = blockIdx.x;
    const int tid = threadIdx.x;
    if (bx < 3584) {
        bias_body<7, 16, 14, 28>(rpb0, bt7, bx * 256 + tid);
    } else {
        bias_body<13, 20, 20, 50>(rpb1, bt13, (bx - 3584) * 256 + tid);
    }
}

// ---------------------------------------------------------------------------
// GEMM (exact R12 version — best measured): 128-thread blocks, BM=64 x
// BN=128, cp.async double-buffered, one stage pair in flight.
// ---------------------------------------------------------------------------
__global__ __launch_bounds__(128)
void gemm_tf32(const float* __restrict__ A, const float* __restrict__ B,
               const float* __restrict__ bias, float* __restrict__ C,
               int Kd, int Nd, int qmode, float qscale)
{
    __shared__ uint32_t As[2][64][20];
    __shared__ uint32_t Bs[2][128][20];
    const uint32_t sa = smem_u32(As);
    const uint32_t sbb = smem_u32(Bs);

    const int bm = blockIdx.y << 6;
    const int bn = blockIdx.x << 7;
    const int tid = threadIdx.x;

    const int lrow = tid >> 2;          // 0..31
    const int lkc  = (tid & 3) << 2;    // 0,4,8,12
    const float* Ap0 = A + (size_t)(bm + lrow) * Kd + lkc;
    const float* Ap1 = A + (size_t)(bm + lrow + 32) * Kd + lkc;
    const float* Bp0 = B + (size_t)(bn + lrow) * Kd + lkc;
    const float* Bp1 = B + (size_t)(bn + lrow + 32) * Kd + lkc;
    const float* Bp2 = B + (size_t)(bn + lrow + 64) * Kd + lkc;
    const float* Bp3 = B + (size_t)(bn + lrow + 96) * Kd + lkc;
    const uint32_t da0 = sa  + (uint32_t)(lrow * 20 + lkc) * 4u;
    const uint32_t da1 = sa  + (uint32_t)((lrow + 32) * 20 + lkc) * 4u;
    const uint32_t db0 = sbb + (uint32_t)(lrow * 20 + lkc) * 4u;
    const uint32_t db1 = sbb + (uint32_t)((lrow + 32) * 20 + lkc) * 4u;
    const uint32_t db2 = sbb + (uint32_t)((lrow + 64) * 20 + lkc) * 4u;
    const uint32_t db3 = sbb + (uint32_t)((lrow + 96) * 20 + lkc) * 4u;
    constexpr uint32_t STA = 64 * 20 * 4;
    constexpr uint32_t STBB = 128 * 20 * 4;

    const int wid = tid >> 5;
    const int lane = tid & 31;
    const int wm = (wid >> 1) << 5;     // 0,32
    const int wn = (wid & 1) << 6;      // 0,64
    const int lr = lane >> 2;
    const int lc = lane & 3;

    float acc[2][8][4];
#pragma unroll
    for (int mt = 0; mt < 2; mt++)
#pragma unroll
        for (int nt = 0; nt < 8; nt++)
#pragma unroll
            for (int r = 0; r < 4; r++) acc[mt][nt][r] = 0.f;

#define GSTAGE(it, st)                                                        \
    do {                                                                      \
        const int ko = (it) << 4;                                             \
        asm volatile("cp.async.ca.shared.global [%0], [%1], 16;"              \
                     :: "r"(da0 + (st) * STA), "l"(Ap0 + ko));                \
        asm volatile("cp.async.ca.shared.global [%0], [%1], 16;"              \
                     :: "r"(da1 + (st) * STA), "l"(Ap1 + ko));                \
        asm volatile("cp.async.ca.shared.global [%0], [%1], 16;"              \
                     :: "r"(db0 + (st) * STBB), "l"(Bp0 + ko));               \
        asm volatile("cp.async.ca.shared.global [%0], [%1], 16;"              \
                     :: "r"(db1 + (st) * STBB), "l"(Bp1 + ko));               \
        asm volatile("cp.async.ca.shared.global [%0], [%1], 16;"              \
                     :: "r"(db2 + (st) * STBB), "l"(Bp2 + ko));               \
        asm volatile("cp.async.ca.shared.global [%0], [%1], 16;"              \
                     :: "r"(db3 + (st) * STBB), "l"(Bp3 + ko));               \
        asm volatile("cp.async.commit_group;");                               \
    } while (0)

    const int NIT = Kd >> 4;
    GSTAGE(0, 0);

    for (int it = 0; it < NIT; it++) {
        const int cur = it & 1;
        if (it + 1 < NIT) {
            GSTAGE(it + 1, cur ^ 1);
            asm volatile("cp.async.wait_group 1;");
        } else {
            asm volatile("cp.async.wait_group 0;");
        }
        __syncthreads();
#pragma unroll
        for (int kk = 0; kk < 16; kk += 8) {
            uint32_t af[2][4];
#pragma unroll
            for (int mt = 0; mt < 2; mt++) {
                const int m0 = wm + (mt << 4);
                af[mt][0] = As[cur][m0 + lr][kk + lc];
                af[mt][1] = As[cur][m0 + lr + 8][kk + lc];
                af[mt][2] = As[cur][m0 + lr][kk + lc + 4];
                af[mt][3] = As[cur][m0 + lr + 8][kk + lc + 4];
            }
#pragma unroll
            for (int nt = 0; nt < 8; nt++) {
                const int n0 = wn + (nt << 3);
                uint32_t b0 = Bs[cur][n0 + lr][kk + lc];
                uint32_t b1 = Bs[cur][n0 + lr][kk + lc + 4];
#pragma unroll
                for (int mt = 0; mt < 2; mt++) {
                    asm volatile(
                        "mma.sync.aligned.m16n8k8.row.col.f32.tf32.tf32.f32 "
                        "{%0,%1,%2,%3}, {%4,%5,%6,%7}, {%8,%9}, {%0,%1,%2,%3};\n"
                        : "+f"(acc[mt][nt][0]), "+f"(acc[mt][nt][1]),
                          "+f"(acc[mt][nt][2]), "+f"(acc[mt][nt][3])
                        : "r"(af[mt][0]), "r"(af[mt][1]), "r"(af[mt][2]), "r"(af[mt][3]),
                          "r"(b0), "r"(b1));
                }
            }
        }
        __syncthreads();
    }
#undef GSTAGE

#pragma unroll
    for (int nt = 0; nt < 8; nt++) {
        const int col = bn + wn + (nt << 3) + (lc << 1);
        const float bx = __ldg(&bias[col]);
        const float by = __ldg(&bias[col + 1]);
#pragma unroll
        for (int mt = 0; mt < 2; mt++) {
            const int row = bm + wm + (mt << 4) + lr;
            float v0 = acc[mt][nt][0] + bx;
            float v1 = acc[mt][nt][1] + by;
            float v2 = acc[mt][nt][2] + bx;
            float v3 = acc[mt][nt][3] + by;
            if (qmode) {
                const float sc = (col < 256) ? qscale : 1.f;
                v0 = __uint_as_float(f2tf32(v0 * sc));
                v1 = __uint_as_float(f2tf32(v1 * sc));
                v2 = __uint_as_float(f2tf32(v2 * sc));
                v3 = __uint_as_float(f2tf32(v3 * sc));
            }
            *(float2*)&C[(size_t)row * Nd + col] = make_float2(v0, v1);
            *(float2*)&C[(size_t)(row + 8) * Nd + col] = make_float2(v2, v3);
        }
    }
}

// ---------------------------------------------------------------------------
// Tensor-core NATTEN body (R12 version — known-good, 8x8 tiles).
// ---------------------------------------------------------------------------
template<int K, int UXP, int UXR, int NT, int NC>
__device__ __forceinline__ void natten_body(const float* __restrict__ bias_table,
                                            int head0, int hl)
{
    constexpr int NH = K / 2;
    constexpr int UY = K + 7;
    constexpr int CP = NT * 8;
    constexpr int NTILES = NT * NC;
    constexpr int OQ = 0;             // Qs[32][72]
    constexpr int OK = 2304;          // Ks[CP][36]
    constexpr int OV = OK + CP * 36;  // Vs[CP][40]

    extern __shared__ float sm[];
    uint32_t* smu = (uint32_t*)sm;
    const uint32_t sb = smem_u32(sm);

    const int b    = blockIdx.z;
    const int h    = head0 + hl;
    const int tile = blockIdx.x;
    const int ty = tile >> 3, tx = tile & 7;
    const int uy0 = iclamp(ty * 8 - NH, 0, HH - UY);
    const int ux0 = iclamp(tx * 8 - NH, 0, WW - UY);

    const int tid  = threadIdx.x;
    const int w    = tid >> 5;
    const int lane = tid & 31;
    const int lr = lane >> 2, lc = lane & 3;
    const int m0 = w << 4;

    {
        const int qm = tid >> 1;
        const int kh = (tid & 1) << 4;
        const int qi = ty * 8 + (qm >> 3);
        const int qj = tx * 8 + (qm & 7);
        const uint4* qp = (const uint4*)&g_qkv[(size_t)((b * HH + qi) * WW + qj) * 768 + h * 32 + kh];
#pragma unroll
        for (int v4 = 0; v4 < 4; v4++) {
            uint4 qv = __ldg(&qp[v4]);
            smu[OQ + (kh + v4 * 4 + 0) * 72 + qm] = qv.x;
            smu[OQ + (kh + v4 * 4 + 1) * 72 + qm] = qv.y;
            smu[OQ + (kh + v4 * 4 + 2) * 72 + qm] = qv.z;
            smu[OQ + (kh + v4 * 4 + 3) * 72 + qm] = qv.w;
        }
    }
    __syncthreads();

    uint32_t qf[4][4];
#pragma unroll
    for (int s = 0; s < 4; s++) {
        qf[s][0] = smu[OQ + (8 * s + lc) * 72 + m0 + lr];
        qf[s][1] = smu[OQ + (8 * s + lc) * 72 + m0 + lr + 8];
        qf[s][2] = smu[OQ + (8 * s + lc + 4) * 72 + m0 + lr];
        qf[s][3] = smu[OQ + (8 * s + lc + 4) * 72 + m0 + lr + 8];
    }

    float mr0 = -1e28f, mr1 = -1e28f, l0 = 0.f, l1 = 0.f;
    float o[4][4];
#pragma unroll
    for (int nt = 0; nt < 4; nt++)
#pragma unroll
        for (int r = 0; r < 4; r++) o[nt][r] = 0.f;

    const float4* bt = (const float4*)bias_table +
        ((size_t)(((hl * 64 + tile) * 4 + w) * 32 + lane)) * NTILES;

    const int s1 = (lane & 28) | ((lane & 3) >> 1);
    const int s2 = s1 + 2;
    const bool oddc = (lane & 1);

    for (int c = 0; c < NC; c++) {
        __syncthreads();
        {
            const int e = tid & 7;
#pragma unroll 1
            for (int p = tid >> 3; p < CP; p += 16) {
                const int n = c * CP + p;
                const int uy = n / UXP, ux = n % UXP;
                const int y = uy0 + uy;
                const int x = min(ux0 + ux, WW - 1);
                const float* kp = &g_qkv[(size_t)((b * HH + y) * WW + x) * 768 + 256 + h * 32 + e * 4];
                const uint32_t ks = sb + (uint32_t)(OK + p * 36 + 4 * e) * 4u;
                const uint32_t vs = sb + (uint32_t)(OV + p * 40 + 4 * e) * 4u;
                asm volatile("cp.async.ca.shared.global [%0], [%1], 16;" :: "r"(ks), "l"(kp));
                asm volatile("cp.async.ca.shared.global [%0], [%1], 16;" :: "r"(vs), "l"(kp + 256));
            }
            asm volatile("cp.async.commit_group;");
            asm volatile("cp.async.wait_group 0;");
        }
        __syncthreads();

        float s[NT][4];
#pragma unroll
        for (int t = 0; t < NT; t++)
#pragma unroll
            for (int r = 0; r < 4; r++) s[t][r] = 0.f;
#pragma unroll
        for (int t = 0; t < NT; t++) {
#pragma unroll
            for (int kk = 0; kk < 4; kk++) {
                uint32_t b0 = smu[OK + (8 * t + lr) * 36 + 8 * kk + lc];
                uint32_t b1 = smu[OK + (8 * t + lr) * 36 + 8 * kk + lc + 4];
                asm volatile(
                    "mma.sync.aligned.m16n8k8.row.col.f32.tf32.tf32.f32 "
                    "{%0,%1,%2,%3}, {%4,%5,%6,%7}, {%8,%9}, {%0,%1,%2,%3};\n"
                    : "+f"(s[t][0]), "+f"(s[t][1]), "+f"(s[t][2]), "+f"(s[t][3])
                    : "r"(qf[kk][0]), "r"(qf[kk][1]), "r"(qf[kk][2]), "r"(qf[kk][3]),
                      "r"(b0), "r"(b1));
            }
        }
#pragma unroll
        for (int t = 0; t < NT; t++) {
            float4 bv = __ldg(&bt[c * NT + t]);
            s[t][0] += bv.x; s[t][1] += bv.y; s[t][2] += bv.z; s[t][3] += bv.w;
        }
        float rm0 = -1e30f, rm1 = -1e30f;
#pragma unroll
        for (int t = 0; t < NT; t++) {
            rm0 = fmaxf(rm0, fmaxf(s[t][0], s[t][1]));
            rm1 = fmaxf(rm1, fmaxf(s[t][2], s[t][3]));
        }
        rm0 = fmaxf(rm0, __shfl_xor_sync(0xffffffffu, rm0, 1));
        rm0 = fmaxf(rm0, __shfl_xor_sync(0xffffffffu, rm0, 2));
        rm1 = fmaxf(rm1, __shfl_xor_sync(0xffffffffu, rm1, 1));
        rm1 = fmaxf(rm1, __shfl_xor_sync(0xffffffffu, rm1, 2));
        const float nm0 = fmaxf(mr0, rm0);
        const float nm1 = fmaxf(mr1, rm1);
        const float c0 = __expf(mr0 - nm0);
        const float c1 = __expf(mr1 - nm1);
        mr0 = nm0; mr1 = nm1;
        l0 *= c0; l1 *= c1;
#pragma unroll
        for (int nt = 0; nt < 4; nt++) {
            o[nt][0] *= c0; o[nt][1] *= c0;
            o[nt][2] *= c1; o[nt][3] *= c1;
        }
#pragma unroll
        for (int t = 0; t < NT; t++) {
            const float p0 = __expf(s[t][0] - nm0);
            const float p1 = __expf(s[t][1] - nm0);
            const float p2 = __expf(s[t][2] - nm1);
            const float p3 = __expf(s[t][3] - nm1);
            l0 += p0 + p1; l1 += p2 + p3;
            const uint32_t u0 = f2tf32(p0), u1 = f2tf32(p1);
            const uint32_t u2 = f2tf32(p2), u3 = f2tf32(p3);
            const uint32_t x0 = __shfl_sync(0xffffffffu, u0, s1);
            const uint32_t y0 = __shfl_sync(0xffffffffu, u1, s1);
            const uint32_t x1 = __shfl_sync(0xffffffffu, u2, s1);
            const uint32_t y1 = __shfl_sync(0xffffffffu, u3, s1);
            const uint32_t x2 = __shfl_sync(0xffffffffu, u0, s2);
            const uint32_t y2 = __shfl_sync(0xffffffffu, u1, s2);
            const uint32_t x3 = __shfl_sync(0xffffffffu, u2, s2);
            const uint32_t y3 = __shfl_sync(0xffffffffu, u3, s2);
            const uint32_t pa0 = oddc ? y0 : x0;
            const uint32_t pa1 = oddc ? y1 : x1;
            const uint32_t pa2 = oddc ? y2 : x2;
            const uint32_t pa3 = oddc ? y3 : x3;
#pragma unroll
            for (int nt = 0; nt < 4; nt++) {
                uint32_t b0 = smu[OV + (8 * t + lc) * 40 + 8 * nt + lr];
                uint32_t b1 = smu[OV + (8 * t + lc + 4) * 40 + 8 * nt + lr];
                asm volatile(
                    "mma.sync.aligned.m16n8k8.row.col.f32.tf32.tf32.f32 "
                    "{%0,%1,%2,%3}, {%4,%5,%6,%7}, {%8,%9}, {%0,%1,%2,%3};\n"
                    : "+f"(o[nt][0]), "+f"(o[nt][1]), "+f"(o[nt][2]), "+f"(o[nt][3])
                    : "r"(pa0), "r"(pa1), "r"(pa2), "r"(pa3), "r"(b0), "r"(b1));
            }
        }
    }

    l0 += __shfl_xor_sync(0xffffffffu, l0, 1);
    l0 += __shfl_xor_sync(0xffffffffu, l0, 2);
    l1 += __shfl_xor_sync(0xffffffffu, l1, 1);
    l1 += __shfl_xor_sync(0xffffffffu, l1, 2);
    const float inv0 = 1.f / l0;
    const float inv1 = 1.f / l1;
    const int i0 = ty * 8 + 2 * w;
    const int j  = tx * 8 + lr;
    float* y0 = &g_y[(size_t)((b * HH + i0) * WW + j) * 256 + h * 32];
    float* y1 = &g_y[(size_t)((b * HH + i0 + 1) * WW + j) * 256 + h * 32];
#pragma unroll
    for (int nt = 0; nt < 4; nt++) {
        const int d = 8 * nt + 2 * lc;
        *(float2*)&y0[d] = make_float2(
            __uint_as_float(f2tf32(o[nt][0] * inv0)),
            __uint_as_float(f2tf32(o[nt][1] * inv0)));
        *(float2*)&y1[d] = make_float2(
            __uint_as_float(f2tf32(o[nt][2] * inv1)),
            __uint_as_float(f2tf32(o[nt][3] * inv1)));
    }
}

// One launch for all 8 heads: blockIdx.y 0-3 -> K7 path, 4-7 -> K13 path.
__global__ __launch_bounds__(128)
void natten_all(const float* __restrict__ bt7, const float* __restrict__ bt13)
{
    const int hl = blockIdx.y;
    if (hl < 4) natten_body<7, 16, 14, 7, 4>(bt7, 0, hl);
    else        natten_body<13, 20, 20, 10, 5>(bt13, 4, hl - 4);
}

// ---------------------------------------------------------------------------
extern "C" void kernel_launch(void* const* d_in, const int* in_sizes, int n_in,
                              void* d_out, int out_size)
{
    const float* x      = (const float*)d_in[0];
    const float* w_qkv  = (const float*)d_in[1];
    const float* b_qkv  = (const float*)d_in[2];
    const float* rpb0   = (const float*)d_in[3];
    const float* rpb1   = (const float*)d_in[4];
    const float* w_proj = (const float*)d_in[5];
    const float* b_proj = (const float*)d_in[6];
    float* out = (float*)d_out;

    float *qkv = nullptr, *y = nullptr, *xt = nullptr, *wt = nullptr;
    float *bt7 = nullptr, *bt13 = nullptr;
    cudaGetSymbolAddress((void**)&qkv,  g_qkv);
    cudaGetSymbolAddress((void**)&y,    g_y);
    cudaGetSymbolAddress((void**)&xt,   g_xt);
    cudaGetSymbolAddress((void**)&wt,   g_wt);
    cudaGetSymbolAddress((void**)&bt7,  g_bias7);
    cudaGetSymbolAddress((void**)&bt13, g_bias13);
    float* wqt = wt;            // 768x256
    float* wpt = wt + 196608;   // 256x256

    // Lazy one-time stream/event setup (first call is outside graph capture;
    // captured calls only record/wait/launch — a legal fork-join pattern).
    static cudaStream_t s2 = nullptr;
    static cudaEvent_t ev_fork = nullptr, ev_join = nullptr;
    if (s2 == nullptr) {
        cudaStreamCreateWithFlags(&s2, cudaStreamNonBlocking);
        cudaEventCreateWithFlags(&ev_fork, cudaEventDisableTiming);
        cudaEventCreateWithFlags(&ev_join, cudaEventDisableTiming);
    }

    // natten needs 33536 B dynamic smem (K13 path)
    cudaFuncSetAttribute(natten_all,
                         cudaFuncAttributeMaxDynamicSharedMemorySize, 33536);

    // ---- fork: bias tables on s2, overlapping round + QKV GEMM ----
    cudaEventRecord(ev_fork, 0);
    cudaStreamWaitEvent(s2, ev_fork, 0);
    prep_bias<<<9984, 256, 0, s2>>>(rpb0, rpb1, bt7, bt13);
    cudaEventRecord(ev_join, s2);

    // main stream: rounding then QKV GEMM
    prep_round<<<8448, 256>>>(x, w_qkv, w_proj, xt, wqt, wpt);
    gemm_tf32<<<dim3(6, 512), 128>>>(xt, wqt, b_qkv, qkv, 256, 768,
                                     1, 0.17677669529663687f);

    // ---- join before natten (needs bias tables) ----
    cudaStreamWaitEvent(0, ev_join, 0);

    // 2) neighborhood attention, both window sizes in one launch
    natten_all<<<dim3(64, 8, 8), 128, 33536>>>(bt7, bt13);

    // 3) Projection GEMM
    gemm_tf32<<<dim3(2, 512), 128>>>(y, wpt, b_proj, out, 256, 256, 0, 0.f);
}

// round 17
// speedup vs baseline: 1.0182x; 1.0182x over previous
#include <cuda_runtime.h>
#include <cstdint>

#define BB 8
#define HH 64
#define WW 64

// Scratch: qkv [32768 x 768] (tf32 bits; q pre-scaled; k-section dim-pair
// interleaved), y [32768 x 256], xt/wt rounded copies, permuted b_qkv,
// bias tables in mma-frag order.
__device__ float g_qkv[25165824];
__device__ float g_y[8388608];
__device__ float g_xt[8388608];
__device__ float g_wt[262144];       // w_qkv_t [768x256] + w_proj_t [256x256]
__device__ float g_bq[768];          // permuted b_qkv
__device__ float g_bias7[3670016];   // 4h*64t*4w*32l*28nt*4
__device__ float g_bias13[7864320];  // 4h*64t*4w*32l*50nt*4 (6553600 used)

__device__ __forceinline__ uint32_t f2tf32(float x) {
    uint32_t u;
    asm("cvt.rna.tf32.f32 %0, %1;" : "=r"(u) : "f"(x));
    return u;
}
__device__ __forceinline__ int iclamp(int v, int lo, int hi) {
    return min(max(v, lo), hi);
}
__device__ __forceinline__ uint32_t smem_u32(const void* p) {
    uint32_t a;
    asm("{ .reg .u64 t; cvta.to.shared.u64 t, %1; cvt.u32.u64 %0, t; }"
        : "=r"(a) : "l"(p));
    return a;
}

// k-section row permutation: output position p (within an 8-group) holds
// source dim ((p&1)<<2) | ((p>>1)&3). Identity outside rows [256,512).
__device__ __forceinline__ int kperm_row(int row) {
    if (row >= 256 && row < 512) {
        const int p7 = row & 7;
        return (row & ~7) | (((p7 & 1) << 2) | ((p7 >> 1) & 3));
    }
    return row;
}

// ---------------------------------------------------------------------------
// Prep bodies
// ---------------------------------------------------------------------------
__device__ __forceinline__ void round_body(const float4* __restrict__ src,
                                           float4* __restrict__ dst,
                                           int i, int n4)
{
    if (i >= n4) return;
    float4 v = __ldg(&src[i]);
    v.x = __uint_as_float(f2tf32(v.x));
    v.y = __uint_as_float(f2tf32(v.y));
    v.z = __uint_as_float(f2tf32(v.z));
    v.w = __uint_as_float(f2tf32(v.w));
    dst[i] = v;
}

// w_qkv rounding with k-section row permutation (768 rows x 256 cols).
__device__ __forceinline__ void round_wq_body(const float* __restrict__ src,
                                              float4* __restrict__ dst, int i)
{
    if (i >= 49152) return;
    const int row = i >> 6;
    const int col4 = i & 63;
    const int srow = kperm_row(row);
    float4 v = __ldg(&((const float4*)src)[srow * 64 + col4]);
    v.x = __uint_as_float(f2tf32(v.x));
    v.y = __uint_as_float(f2tf32(v.y));
    v.z = __uint_as_float(f2tf32(v.z));
    v.w = __uint_as_float(f2tf32(v.w));
    dst[i] = v;
}

template<int K, int UXP, int UXR, int NTILES>
__device__ __forceinline__ void bias_body(const float* __restrict__ rpb,
                                          float* __restrict__ table, int gid)
{
    constexpr int NH = K / 2;
    constexpr int RP = 2 * K - 1;
    constexpr int UY = K + 7;
    const int t    = gid % NTILES;
    int r1 = gid / NTILES;
    const int lane = r1 & 31; r1 >>= 5;
    const int w    = r1 & 3;  r1 >>= 2;
    const int tile = r1 & 63; r1 >>= 6;
    const int h    = r1;
    const int ty = tile >> 3, tx = tile & 7;
    const int lr = lane >> 2, lc = lane & 3;
    const int uy0 = iclamp(ty * 8 - NH, 0, HH - UY);
    const int ux0 = iclamp(tx * 8 - NH, 0, WW - UY);

    float v[4];
#pragma unroll
    for (int r = 0; r < 4; r++) {
        const int m = w * 16 + lr + ((r >> 1) << 3);
        const int n = t * 8 + (lc << 1) + (r & 1);
        const int i = ty * 8 + (m >> 3);
        const int j = tx * 8 + (m & 7);
        const int si = iclamp(i - NH, 0, HH - K);
        const int sj = iclamp(j - NH, 0, WW - K);
        const int uy = n / UXP, ux = n % UXP;
        const int y = uy0 + uy, x = ux0 + ux;
        bool ok = (ux < UXR) && (y >= si) && (y < si + K) && (x >= sj) && (x < sj + K);
        v[r] = ok ? rpb[((size_t)h * RP + (y - i + K - 1)) * RP + (x - j + K - 1)]
                  : -1e30f;
    }
    *(float4*)&table[(size_t)gid * 4] = make_float4(v[0], v[1], v[2], v[3]);
}

// ranges: [0,8192) round x | [8192,8384) round wq (k-permuted) |
//         [8384,8448) round wp | [8448,8451) permute bq |
//         [8451,12035) bias7 | [12035,18435) bias13
__global__ __launch_bounds__(256)
void prep_all(const float* __restrict__ x,
              const float* __restrict__ w_qkv,
              const float* __restrict__ b_qkv,
              const float* __restrict__ w_proj,
              const float* __restrict__ rpb0,
              const float* __restrict__ rpb1,
              float* __restrict__ xt, float* __restrict__ wqt,
              float* __restrict__ wpt, float* __restrict__ bq,
              float* __restrict__ bt7, float* __restrict__ bt13)
{
    const int bx = blockIdx.x;
    const int tid = threadIdx.x;
    if (bx < 8192) {
        round_body((const float4*)x, (float4*)xt, bx * 256 + tid, 2097152);
    } else if (bx < 8384) {
        round_wq_body(w_qkv, (float4*)wqt, (bx - 8192) * 256 + tid);
    } else if (bx < 8448) {
        round_body((const float4*)w_proj, (float4*)wpt, (bx - 8384) * 256 + tid, 16384);
    } else if (bx < 8451) {
        const int i = (bx - 8448) * 256 + tid;
        if (i < 768) bq[i] = __ldg(&b_qkv[kperm_row(i)]);
    } else if (bx < 12035) {
        bias_body<7, 16, 14, 28>(rpb0, bt7, (bx - 8451) * 256 + tid);
    } else {
        bias_body<13, 20, 20, 50>(rpb1, bt13, (bx - 12035) * 256 + tid);
    }
}

// ---------------------------------------------------------------------------
// GEMM (exact R12 version — best measured): 128-thread blocks, BM=64 x
// BN=128, cp.async double-buffered.
// ---------------------------------------------------------------------------
__global__ __launch_bounds__(128)
void gemm_tf32(const float* __restrict__ A, const float* __restrict__ B,
               const float* __restrict__ bias, float* __restrict__ C,
               int Kd, int Nd, int qmode, float qscale)
{
    __shared__ uint32_t As[2][64][20];
    __shared__ uint32_t Bs[2][128][20];
    const uint32_t sa = smem_u32(As);
    const uint32_t sbb = smem_u32(Bs);

    const int bm = blockIdx.y << 6;
    const int bn = blockIdx.x << 7;
    const int tid = threadIdx.x;

    const int lrow = tid >> 2;
    const int lkc  = (tid & 3) << 2;
    const float* Ap0 = A + (size_t)(bm + lrow) * Kd + lkc;
    const float* Ap1 = A + (size_t)(bm + lrow + 32) * Kd + lkc;
    const float* Bp0 = B + (size_t)(bn + lrow) * Kd + lkc;
    const float* Bp1 = B + (size_t)(bn + lrow + 32) * Kd + lkc;
    const float* Bp2 = B + (size_t)(bn + lrow + 64) * Kd + lkc;
    const float* Bp3 = B + (size_t)(bn + lrow + 96) * Kd + lkc;
    const uint32_t da0 = sa  + (uint32_t)(lrow * 20 + lkc) * 4u;
    const uint32_t da1 = sa  + (uint32_t)((lrow + 32) * 20 + lkc) * 4u;
    const uint32_t db0 = sbb + (uint32_t)(lrow * 20 + lkc) * 4u;
    const uint32_t db1 = sbb + (uint32_t)((lrow + 32) * 20 + lkc) * 4u;
    const uint32_t db2 = sbb + (uint32_t)((lrow + 64) * 20 + lkc) * 4u;
    const uint32_t db3 = sbb + (uint32_t)((lrow + 96) * 20 + lkc) * 4u;
    constexpr uint32_t STA = 64 * 20 * 4;
    constexpr uint32_t STBB = 128 * 20 * 4;

    const int wid = tid >> 5;
    const int lane = tid & 31;
    const int wm = (wid >> 1) << 5;
    const int wn = (wid & 1) << 6;
    const int lr = lane >> 2;
    const int lc = lane & 3;

    float acc[2][8][4];
#pragma unroll
    for (int mt = 0; mt < 2; mt++)
#pragma unroll
        for (int nt = 0; nt < 8; nt++)
#pragma unroll
            for (int r = 0; r < 4; r++) acc[mt][nt][r] = 0.f;

#define GSTAGE(it, st)                                                        \
    do {                                                                      \
        const int ko = (it) << 4;                                             \
        asm volatile("cp.async.ca.shared.global [%0], [%1], 16;"              \
                     :: "r"(da0 + (st) * STA), "l"(Ap0 + ko));                \
        asm volatile("cp.async.ca.shared.global [%0], [%1], 16;"              \
                     :: "r"(da1 + (st) * STA), "l"(Ap1 + ko));                \
        asm volatile("cp.async.ca.shared.global [%0], [%1], 16;"              \
                     :: "r"(db0 + (st) * STBB), "l"(Bp0 + ko));               \
        asm volatile("cp.async.ca.shared.global [%0], [%1], 16;"              \
                     :: "r"(db1 + (st) * STBB), "l"(Bp1 + ko));               \
        asm volatile("cp.async.ca.shared.global [%0], [%1], 16;"              \
                     :: "r"(db2 + (st) * STBB), "l"(Bp2 + ko));               \
        asm volatile("cp.async.ca.shared.global [%0], [%1], 16;"              \
                     :: "r"(db3 + (st) * STBB), "l"(Bp3 + ko));               \
        asm volatile("cp.async.commit_group;");                               \
    } while (0)

    const int NIT = Kd >> 4;
    GSTAGE(0, 0);

    for (int it = 0; it < NIT; it++) {
        const int cur = it & 1;
        if (it + 1 < NIT) {
            GSTAGE(it + 1, cur ^ 1);
            asm volatile("cp.async.wait_group 1;");
        } else {
            asm volatile("cp.async.wait_group 0;");
        }
        __syncthreads();
#pragma unroll
        for (int kk = 0; kk < 16; kk += 8) {
            uint32_t af[2][4];
#pragma unroll
            for (int mt = 0; mt < 2; mt++) {
                const int m0 = wm + (mt << 4);
                af[mt][0] = As[cur][m0 + lr][kk + lc];
                af[mt][1] = As[cur][m0 + lr + 8][kk + lc];
                af[mt][2] = As[cur][m0 + lr][kk + lc + 4];
                af[mt][3] = As[cur][m0 + lr + 8][kk + lc + 4];
            }
#pragma unroll
            for (int nt = 0; nt < 8; nt++) {
                const int n0 = wn + (nt << 3);
                uint32_t b0 = Bs[cur][n0 + lr][kk + lc];
                uint32_t b1 = Bs[cur][n0 + lr][kk + lc + 4];
#pragma unroll
                for (int mt = 0; mt < 2; mt++) {
                    asm volatile(
                        "mma.sync.aligned.m16n8k8.row.col.f32.tf32.tf32.f32 "
                        "{%0,%1,%2,%3}, {%4,%5,%6,%7}, {%8,%9}, {%0,%1,%2,%3};\n"
                        : "+f"(acc[mt][nt][0]), "+f"(acc[mt][nt][1]),
                          "+f"(acc[mt][nt][2]), "+f"(acc[mt][nt][3])
                        : "r"(af[mt][0]), "r"(af[mt][1]), "r"(af[mt][2]), "r"(af[mt][3]),
                          "r"(b0), "r"(b1));
                }
            }
        }
        __syncthreads();
    }
#undef GSTAGE

#pragma unroll
    for (int nt = 0; nt < 8; nt++) {
        const int col = bn + wn + (nt << 3) + (lc << 1);
        const float bx = __ldg(&bias[col]);
        const float by = __ldg(&bias[col + 1]);
#pragma unroll
        for (int mt = 0; mt < 2; mt++) {
            const int row = bm + wm + (mt << 4) + lr;
            float v0 = acc[mt][nt][0] + bx;
            float v1 = acc[mt][nt][1] + by;
            float v2 = acc[mt][nt][2] + bx;
            float v3 = acc[mt][nt][3] + by;
            if (qmode) {
                const float sc = (col < 256) ? qscale : 1.f;
                v0 = __uint_as_float(f2tf32(v0 * sc));
                v1 = __uint_as_float(f2tf32(v1 * sc));
                v2 = __uint_as_float(f2tf32(v2 * sc));
                v3 = __uint_as_float(f2tf32(v3 * sc));
            }
            *(float2*)&C[(size_t)row * Nd + col] = make_float2(v0, v1);
            *(float2*)&C[(size_t)(row + 8) * Nd + col] = make_float2(v2, v3);
        }
    }
}

// ---------------------------------------------------------------------------
// Tensor-core NATTEN. K is stored dim-pair-interleaved (via weight-row
// permutation), so S-mma K-frags are LDS.64 at Ks[pos][8kk+2lc], stride 40
// (banks 8*lr+2*lc — conflict-free). Otherwise exact R12.
// ---------------------------------------------------------------------------
template<int K, int UXP, int UXR, int NT, int NC>
__device__ __forceinline__ void natten_body(const float* __restrict__ bias_table,
                                            int head0, int hl)
{
    constexpr int NH = K / 2;
    constexpr int UY = K + 7;
    constexpr int CP = NT * 8;
    constexpr int NTILES = NT * NC;
    constexpr int OQ = 0;             // Qs[32][72]
    constexpr int OK = 2304;          // Ks[CP][40]
    constexpr int OV = OK + CP * 40;  // Vs[CP][40]

    extern __shared__ float sm[];
    uint32_t* smu = (uint32_t*)sm;
    const uint32_t sb = smem_u32(sm);

    const int b    = blockIdx.z;
    const int h    = head0 + hl;
    const int tile = blockIdx.x;
    const int ty = tile >> 3, tx = tile & 7;
    const int uy0 = iclamp(ty * 8 - NH, 0, HH - UY);
    const int ux0 = iclamp(tx * 8 - NH, 0, WW - UY);

    const int tid  = threadIdx.x;
    const int w    = tid >> 5;
    const int lane = tid & 31;
    const int lr = lane >> 2, lc = lane & 3;
    const int m0 = w << 4;

    {
        const int qm = tid >> 1;
        const int kh = (tid & 1) << 4;
        const int qi = ty * 8 + (qm >> 3);
        const int qj = tx * 8 + (qm & 7);
        const uint4* qp = (const uint4*)&g_qkv[(size_t)((b * HH + qi) * WW + qj) * 768 + h * 32 + kh];
#pragma unroll
        for (int v4 = 0; v4 < 4; v4++) {
            uint4 qv = __ldg(&qp[v4]);
            smu[OQ + (kh + v4 * 4 + 0) * 72 + qm] = qv.x;
            smu[OQ + (kh + v4 * 4 + 1) * 72 + qm] = qv.y;
            smu[OQ + (kh + v4 * 4 + 2) * 72 + qm] = qv.z;
            smu[OQ + (kh + v4 * 4 + 3) * 72 + qm] = qv.w;
        }
    }
    __syncthreads();

    uint32_t qf[4][4];
#pragma unroll
    for (int s = 0; s < 4; s++) {
        qf[s][0] = smu[OQ + (8 * s + lc) * 72 + m0 + lr];
        qf[s][1] = smu[OQ + (8 * s + lc) * 72 + m0 + lr + 8];
        qf[s][2] = smu[OQ + (8 * s + lc + 4) * 72 + m0 + lr];
        qf[s][3] = smu[OQ + (8 * s + lc + 4) * 72 + m0 + lr + 8];
    }

    float mr0 = -1e28f, mr1 = -1e28f, l0 = 0.f, l1 = 0.f;
    float o[4][4];
#pragma unroll
    for (int nt = 0; nt < 4; nt++)
#pragma unroll
        for (int r = 0; r < 4; r++) o[nt][r] = 0.f;

    const float4* bt = (const float4*)bias_table +
        ((size_t)(((hl * 64 + tile) * 4 + w) * 32 + lane)) * NTILES;

    const int s1 = (lane & 28) | ((lane & 3) >> 1);
    const int s2 = s1 + 2;
    const bool oddc = (lane & 1);

    for (int c = 0; c < NC; c++) {
        __syncthreads();
        {
            const int e = tid & 7;
#pragma unroll 1
            for (int p = tid >> 3; p < CP; p += 16) {
                const int n = c * CP + p;
                const int uy = n / UXP, ux = n % UXP;
                const int y = uy0 + uy;
                const int x = min(ux0 + ux, WW - 1);
                const float* kp = &g_qkv[(size_t)((b * HH + y) * WW + x) * 768 + 256 + h * 32 + e * 4];
                const uint32_t ks = sb + (uint32_t)(OK + p * 40 + 4 * e) * 4u;
                const uint32_t vs = sb + (uint32_t)(OV + p * 40 + 4 * e) * 4u;
                asm volatile("cp.async.ca.shared.global [%0], [%1], 16;" :: "r"(ks), "l"(kp));
                asm volatile("cp.async.ca.shared.global [%0], [%1], 16;" :: "r"(vs), "l"(kp + 256));
            }
            asm volatile("cp.async.commit_group;");
            asm volatile("cp.async.wait_group 0;");
        }
        __syncthreads();

        float s[NT][4];
#pragma unroll
        for (int t = 0; t < NT; t++)
#pragma unroll
            for (int r = 0; r < 4; r++) s[t][r] = 0.f;
#pragma unroll
        for (int t = 0; t < NT; t++) {
#pragma unroll
            for (int kk = 0; kk < 4; kk++) {
                uint2 bb = *(const uint2*)&smu[OK + (8 * t + lr) * 40 + 8 * kk + 2 * lc];
                asm volatile(
                    "mma.sync.aligned.m16n8k8.row.col.f32.tf32.tf32.f32 "
                    "{%0,%1,%2,%3}, {%4,%5,%6,%7}, {%8,%9}, {%0,%1,%2,%3};\n"
                    : "+f"(s[t][0]), "+f"(s[t][1]), "+f"(s[t][2]), "+f"(s[t][3])
                    : "r"(qf[kk][0]), "r"(qf[kk][1]), "r"(qf[kk][2]), "r"(qf[kk][3]),
                      "r"(bb.x), "r"(bb.y));
            }
        }
#pragma unroll
        for (int t = 0; t < NT; t++) {
            float4 bv = __ldg(&bt[c * NT + t]);
            s[t][0] += bv.x; s[t][1] += bv.y; s[t][2] += bv.z; s[t][3] += bv.w;
        }
        float rm0 = -1e30f, rm1 = -1e30f;
#pragma unroll
        for (int t = 0; t < NT; t++) {
            rm0 = fmaxf(rm0, fmaxf(s[t][0], s[t][1]));
            rm1 = fmaxf(rm1, fmaxf(s[t][2], s[t][3]));
        }
        rm0 = fmaxf(rm0, __shfl_xor_sync(0xffffffffu, rm0, 1));
        rm0 = fmaxf(rm0, __shfl_xor_sync(0xffffffffu, rm0, 2));
        rm1 = fmaxf(rm1, __shfl_xor_sync(0xffffffffu, rm1, 1));
        rm1 = fmaxf(rm1, __shfl_xor_sync(0xffffffffu, rm1, 2));
        const float nm0 = fmaxf(mr0, rm0);
        const float nm1 = fmaxf(mr1, rm1);
        const float c0 = __expf(mr0 - nm0);
        const float c1 = __expf(mr1 - nm1);
        mr0 = nm0; mr1 = nm1;
        l0 *= c0; l1 *= c1;
#pragma unroll
        for (int nt = 0; nt < 4; nt++) {
            o[nt][0] *= c0; o[nt][1] *= c0;
            o[nt][2] *= c1; o[nt][3] *= c1;
        }
#pragma unroll
        for (int t = 0; t < NT; t++) {
            const float p0 = __expf(s[t][0] - nm0);
            const float p1 = __expf(s[t][1] - nm0);
            const float p2 = __expf(s[t][2] - nm1);
            const float p3 = __expf(s[t][3] - nm1);
            l0 += p0 + p1; l1 += p2 + p3;
            const uint32_t u0 = f2tf32(p0), u1 = f2tf32(p1);
            const uint32_t u2 = f2tf32(p2), u3 = f2tf32(p3);
            const uint32_t x0 = __shfl_sync(0xffffffffu, u0, s1);
            const uint32_t y0 = __shfl_sync(0xffffffffu, u1, s1);
            const uint32_t x1 = __shfl_sync(0xffffffffu, u2, s1);
            const uint32_t y1 = __shfl_sync(0xffffffffu, u3, s1);
            const uint32_t x2 = __shfl_sync(0xffffffffu, u0, s2);
            const uint32_t y2 = __shfl_sync(0xffffffffu, u1, s2);
            const uint32_t x3 = __shfl_sync(0xffffffffu, u2, s2);
            const uint32_t y3 = __shfl_sync(0xffffffffu, u3, s2);
            const uint32_t pa0 = oddc ? y0 : x0;
            const uint32_t pa1 = oddc ? y1 : x1;
            const uint32_t pa2 = oddc ? y2 : x2;
            const uint32_t pa3 = oddc ? y3 : x3;
#pragma unroll
            for (int nt = 0; nt < 4; nt++) {
                uint32_t b0 = smu[OV + (8 * t + lc) * 40 + 8 * nt + lr];
                uint32_t b1 = smu[OV + (8 * t + lc + 4) * 40 + 8 * nt + lr];
                asm volatile(
                    "mma.sync.aligned.m16n8k8.row.col.f32.tf32.tf32.f32 "
                    "{%0,%1,%2,%3}, {%4,%5,%6,%7}, {%8,%9}, {%0,%1,%2,%3};\n"
                    : "+f"(o[nt][0]), "+f"(o[nt][1]), "+f"(o[nt][2]), "+f"(o[nt][3])
                    : "r"(pa0), "r"(pa1), "r"(pa2), "r"(pa3), "r"(b0), "r"(b1));
            }
        }
    }

    l0 += __shfl_xor_sync(0xffffffffu, l0, 1);
    l0 += __shfl_xor_sync(0xffffffffu, l0, 2);
    l1 += __shfl_xor_sync(0xffffffffu, l1, 1);
    l1 += __shfl_xor_sync(0xffffffffu, l1, 2);
    const float inv0 = 1.f / l0;
    const float inv1 = 1.f / l1;
    const int i0 = ty * 8 + 2 * w;
    const int j  = tx * 8 + lr;
    float* y0 = &g_y[(size_t)((b * HH + i0) * WW + j) * 256 + h * 32];
    float* y1 = &g_y[(size_t)((b * HH + i0 + 1) * WW + j) * 256 + h * 32];
#pragma unroll
    for (int nt = 0; nt < 4; nt++) {
        const int d = 8 * nt + 2 * lc;
        *(float2*)&y0[d] = make_float2(
            __uint_as_float(f2tf32(o[nt][0] * inv0)),
            __uint_as_float(f2tf32(o[nt][1] * inv0)));
        *(float2*)&y1[d] = make_float2(
            __uint_as_float(f2tf32(o[nt][2] * inv1)),
            __uint_as_float(f2tf32(o[nt][3] * inv1)));
    }
}

// One launch for all 8 heads: blockIdx.y 0-3 -> K7 path, 4-7 -> K13 path.
__global__ __launch_bounds__(128)
void natten_all(const float* __restrict__ bt7, const float* __restrict__ bt13)
{
    const int hl = blockIdx.y;
    if (hl < 4) natten_body<7, 16, 14, 7, 4>(bt7, 0, hl);
    else        natten_body<13, 20, 20, 10, 5>(bt13, 4, hl - 4);
}

// ---------------------------------------------------------------------------
extern "C" void kernel_launch(void* const* d_in, const int* in_sizes, int n_in,
                              void* d_out, int out_size)
{
    const float* x      = (const float*)d_in[0];
    const float* w_qkv  = (const float*)d_in[1];
    const float* b_qkv  = (const float*)d_in[2];
    const float* rpb0   = (const float*)d_in[3];
    const float* rpb1   = (const float*)d_in[4];
    const float* w_proj = (const float*)d_in[5];
    const float* b_proj = (const float*)d_in[6];
    float* out = (float*)d_out;

    float *qkv = nullptr, *y = nullptr, *xt = nullptr, *wt = nullptr;
    float *bq = nullptr, *bt7 = nullptr, *bt13 = nullptr;
    cudaGetSymbolAddress((void**)&qkv,  g_qkv);
    cudaGetSymbolAddress((void**)&y,    g_y);
    cudaGetSymbolAddress((void**)&xt,   g_xt);
    cudaGetSymbolAddress((void**)&wt,   g_wt);
    cudaGetSymbolAddress((void**)&bq,   g_bq);
    cudaGetSymbolAddress((void**)&bt7,  g_bias7);
    cudaGetSymbolAddress((void**)&bt13, g_bias13);
    float* wqt = wt;            // 768x256
    float* wpt = wt + 196608;   // 256x256

    // natten smem: K13: (2304 + 80*80)*4 = 34816 B
    cudaFuncSetAttribute(natten_all,
                         cudaFuncAttributeMaxDynamicSharedMemorySize, 34816);

    // 0) all prep in one launch (rounding, k-row permutation, bias tables)
    prep_all<<<18435, 256>>>(x, w_qkv, b_qkv, w_proj, rpb0, rpb1,
                             xt, wqt, wpt, bq, bt7, bt13);

    // 1) QKV GEMM (weights k-permuted; bias permuted to match)
    gemm_tf32<<<dim3(6, 512), 128>>>(xt, wqt, bq, qkv, 256, 768,
                                     1, 0.17677669529663687f);

    // 2) neighborhood attention, both window sizes in one launch
    natten_all<<<dim3(64, 8, 8), 128, 34816>>>(bt7, bt13);

    // 3) Projection GEMM
    gemm_tf32<<<dim3(2, 512), 128>>>(y, wpt, b_proj, out, 256, 256, 0, 0.f);
}